// round 15
// baseline (speedup 1.0000x reference)
#include <cuda_runtime.h>
#include <cuda_bf16.h>
#include <cstdint>

#define NB  8
#define NC  256
#define NN  4096
#define MR  128     // query rows per CTA
#define TK  32      // keys per gmem tile
#define NT  512     // threads per CTA

// ---------------- scratch (no allocs allowed) ----------------
__device__ alignas(16) __nv_bfloat16 qth[NB * NN * 32];  // [b][n][d] bf16 hi
__device__ alignas(16) __nv_bfloat16 qtl[NB * NN * 32];  // residual
__device__ alignas(16) __nv_bfloat16 kth[NB * NN * 32];
__device__ alignas(16) __nv_bfloat16 ktl[NB * NN * 32];
__device__ alignas(16) __nv_bfloat16 vv_h[NB * NC * NN]; // [b][ch][n] bf16-hi
__device__ alignas(16) __nv_bfloat16 vv_l[NB * NC * NN]; // bf16 residual

// ---------------- helpers ----------------
__device__ __forceinline__ uint32_t smem_u32(const void* p) {
    uint32_t a;
    asm("{ .reg .u64 t; cvta.to.shared.u64 t, %1; cvt.u32.u64 %0, t; }" : "=r"(a) : "l"(p));
    return a;
}
__device__ __forceinline__ uint32_t bf2pack(float lo, float hi) {
    uint32_t r;
    asm("cvt.rn.bf16x2.f32 %0, %1, %2;" : "=r"(r) : "f"(hi), "f"(lo));
    return r;
}
__device__ __forceinline__ float bfh(float x) {
    return __bfloat162float(__float2bfloat16(x));
}
__device__ __forceinline__ unsigned long long pack2(float a, float b) {
    unsigned long long r;
    asm("mov.b64 %0, {%1, %2};" : "=l"(r) : "f"(a), "f"(b));
    return r;
}
__device__ __forceinline__ void fma2(unsigned long long& d, unsigned long long a, unsigned long long b) {
    asm("fma.rn.f32x2 %0, %1, %2, %0;" : "+l"(d) : "l"(a), "l"(b));
}
__device__ __forceinline__ float2 unpack2(unsigned long long v) {
    float lo, hi;
    asm("mov.b64 {%0, %1}, %2;" : "=f"(lo), "=f"(hi) : "l"(v));
    return make_float2(lo, hi);
}
__device__ __forceinline__ void mma_bf16(float* c, const uint32_t* a,
                                         uint32_t b0, uint32_t b1) {
    asm volatile(
        "mma.sync.aligned.m16n8k16.row.col.f32.bf16.bf16.f32 "
        "{%0,%1,%2,%3},{%4,%5,%6,%7},{%8,%9},{%0,%1,%2,%3};"
        : "+f"(c[0]), "+f"(c[1]), "+f"(c[2]), "+f"(c[3])
        : "r"(a[0]), "r"(a[1]), "r"(a[2]), "r"(a[3]), "r"(b0), "r"(b1));
}
// Validated helper: NON-trans ldmatrix.
__device__ __forceinline__ void ldsm4(uint32_t* r, uint32_t addr) {
    asm volatile("ldmatrix.sync.aligned.m8n8.x4.shared.b16 {%0,%1,%2,%3},[%4];"
                 : "=r"(r[0]), "=r"(r[1]), "=r"(r[2]), "=r"(r[3]) : "r"(addr));
}
__device__ __forceinline__ void cpa16(uint32_t dst, const void* src) {
    asm volatile("cp.async.cg.shared.global [%0], [%1], 16;" :: "r"(dst), "l"(src));
}
__device__ __forceinline__ void cpa8(uint32_t dst, const void* src) {
    asm volatile("cp.async.ca.shared.global [%0], [%1], 8;" :: "r"(dst), "l"(src));
}
#define CP_COMMIT() asm volatile("cp.async.commit_group;" ::: "memory")
#define CP_WAIT0()  asm volatile("cp.async.wait_group 0;" ::: "memory")

// ---------------- projection kernel (byte-identical to R14) -----------------
__global__ void __launch_bounds__(256) proj_kernel(
    const float* __restrict__ x,
    const float* __restrict__ wq, const float* __restrict__ bq,
    const float* __restrict__ wk, const float* __restrict__ bk,
    const float* __restrict__ wv, const float* __restrict__ bv)
{
    __shared__ float xs[32][256];
    __shared__ unsigned long long ws2[32][34];   // [c][o] duplicated (w,w) pairs

    const int b  = blockIdx.z;
    const int n0 = blockIdx.x * 256;
    const int o0 = blockIdx.y * 32;
    const int tid = threadIdx.x;
    const int tx = tid & 63;
    const int ty = tid >> 6;

    unsigned long long accp[8][2];
#pragma unroll
    for (int i = 0; i < 8; i++) { accp[i][0] = 0ull; accp[i][1] = 0ull; }

    for (int cc = 0; cc < NC; cc += 32) {
        __syncthreads();
#pragma unroll
        for (int p = 0; p < 8; p++) {
            int idx = tid + p * 256;
            int c  = idx >> 6;
            int n4 = idx & 63;
            *(float4*)&xs[c][n4 * 4] =
                *(const float4*)&x[(size_t)(b * NC + cc + c) * NN + n0 + n4 * 4];
        }
#pragma unroll
        for (int p = 0; p < 4; p++) {
            int idx = tid + p * 256;
            int o  = idx >> 5;
            int c2 = idx & 31;
            int og = o0 + o;
            const float* wsrc;
            if (og < 32)        wsrc = wq + og * NC;
            else if (og < 64)   wsrc = wk + (og - 32) * NC;
            else                wsrc = wv + (og - 64) * NC;
            float v = wsrc[cc + c2];
            ws2[c2][o] = pack2(v, v);
        }
        __syncthreads();
#pragma unroll
        for (int c = 0; c < 32; c++) {
            ulonglong2 xp = *(const ulonglong2*)&xs[c][tx * 4];
            ulonglong2 wa = *(const ulonglong2*)&ws2[c][ty * 8];
            ulonglong2 wb = *(const ulonglong2*)&ws2[c][ty * 8 + 2];
            ulonglong2 wc = *(const ulonglong2*)&ws2[c][ty * 8 + 4];
            ulonglong2 wd = *(const ulonglong2*)&ws2[c][ty * 8 + 6];
            fma2(accp[0][0], wa.x, xp.x); fma2(accp[0][1], wa.x, xp.y);
            fma2(accp[1][0], wa.y, xp.x); fma2(accp[1][1], wa.y, xp.y);
            fma2(accp[2][0], wb.x, xp.x); fma2(accp[2][1], wb.x, xp.y);
            fma2(accp[3][0], wb.y, xp.x); fma2(accp[3][1], wb.y, xp.y);
            fma2(accp[4][0], wc.x, xp.x); fma2(accp[4][1], wc.x, xp.y);
            fma2(accp[5][0], wc.y, xp.x); fma2(accp[5][1], wc.y, xp.y);
            fma2(accp[6][0], wd.x, xp.x); fma2(accp[6][1], wd.x, xp.y);
            fma2(accp[7][0], wd.y, xp.x); fma2(accp[7][1], wd.y, xp.y);
        }
    }

    float acc[8][4];
#pragma unroll
    for (int i = 0; i < 8; i++) {
        float2 f0 = unpack2(accp[i][0]);
        float2 f1 = unpack2(accp[i][1]);
        acc[i][0] = f0.x; acc[i][1] = f0.y; acc[i][2] = f1.x; acc[i][3] = f1.y;
    }

    if (o0 < 64) {
        const float* bias = (o0 == 0) ? bq : bk;
        __syncthreads();
#pragma unroll
        for (int i = 0; i < 8; i++) {
            int o = ty * 8 + i;
            float bs = bias[o];
#pragma unroll
            for (int j = 0; j < 4; j++)
                xs[o][tx * 4 + j] = acc[i][j] + bs;
        }
        __syncthreads();
        const int n = tid;
        uint32_t hi[16], lo[16];
#pragma unroll
        for (int d2 = 0; d2 < 16; d2++) {
            float v0 = xs[2 * d2][n], v1 = xs[2 * d2 + 1][n];
            float h0 = bfh(v0), h1 = bfh(v1);
            hi[d2] = bf2pack(h0, h1);
            lo[d2] = bf2pack(v0 - h0, v1 - h1);
        }
        __nv_bfloat16* dh = ((o0 == 0) ? qth : kth) + ((size_t)b * NN + n0 + n) * 32;
        __nv_bfloat16* dl = ((o0 == 0) ? qtl : ktl) + ((size_t)b * NN + n0 + n) * 32;
#pragma unroll
        for (int q4 = 0; q4 < 4; q4++) {
            *(uint4*)&dh[q4 * 8] = ((const uint4*)hi)[q4];
            *(uint4*)&dl[q4 * 8] = ((const uint4*)lo)[q4];
        }
    } else {
#pragma unroll
        for (int i = 0; i < 8; i++) {
            int ch = o0 - 64 + ty * 8 + i;
            float bs = bv[ch];
            float vals[4] = {acc[i][0]+bs, acc[i][1]+bs, acc[i][2]+bs, acc[i][3]+bs};
            uint32_t hp[2], lp[2];
#pragma unroll
            for (int p = 0; p < 2; p++) {
                float h0 = bfh(vals[2*p]), h1 = bfh(vals[2*p+1]);
                hp[p] = bf2pack(h0, h1);
                lp[p] = bf2pack(vals[2*p] - h0, vals[2*p+1] - h1);
            }
            size_t off = ((size_t)b * NC + ch) * NN + n0 + tx * 4;
            *(uint32_t*)&vv_h[off]     = hp[0];
            *(uint32_t*)&vv_h[off + 2] = hp[1];
            *(uint32_t*)&vv_l[off]     = lp[0];
            *(uint32_t*)&vv_l[off + 2] = lp[1];
        }
    }
}

// ---------------- fused attention kernel (batched-kg scheduling) ------------
// smem bytes:
//   [0,     20480)  Q stage  bf16 [2 limb][128 rows][40] (80B row stride)
//   [20480, 40960)  K tiles  bf16 [4 buf][2 limb][32 keys][40]
//   [40960, 172032) V tiles  bf16 [4 buf][2 limb][256 ch][32] (period-8 swizzle)
//   epilogue staging [256][68] f32 reuses [0, 69632)
#define QS_OFF 0
#define QL_REL 10240
#define KS_OFF 20480
#define VS_OFF 40960
#define SMEM_BYTES 172032

__global__ void __launch_bounds__(NT, 1) attn_kernel(float* __restrict__ out,
                                                     const float* __restrict__ gamma)
{
    extern __shared__ char smem[];
    const uint32_t sb = smem_u32(smem);

    const int b    = blockIdx.y;
    const int n0   = blockIdx.x * MR;
    const int tid  = threadIdx.x;
    const int w    = tid >> 5;
    const int lane = tid & 31;
    const int mg   = w >> 1;          // row group 0..7 (16 rows each)
    const int cg   = w & 1;           // channel group 0..1 (128 ch each)
    const int lq   = lane >> 2;       // lane/4
    const int lr   = lane & 3;        // lane%4
    const int g    = lane >> 3;       // ldmatrix group
    const int gr   = lane & 7;

    // ---- stage Q (both limbs): 128 rows x 4 segs, one per thread ----
    {
        int row = tid >> 2, seg = tid & 3;
        size_t go = ((size_t)b * NN + n0 + row) * 32 + seg * 8;
        *(uint4*)(smem + QS_OFF +          row * 80 + seg * 16) = *(const uint4*)&qth[go];
        *(uint4*)(smem + QS_OFF + QL_REL + row * 80 + seg * 16) = *(const uint4*)&qtl[go];
    }

    // ---- async tile loads; V swizzle period-8: kqs = kq ^ ((ch>>1)&3) ----
#define LOAD_TILE(BUF, M1) do { \
    { \
        int limb = tid >> 8; \
        int rem  = tid & 255; \
        int key  = rem >> 3, dseg = rem & 7; \
        const __nv_bfloat16* ksrc = limb ? ktl : kth; \
        cpa8(sb + KS_OFF + (BUF) * 5120 + limb * 2560 + key * 80 + dseg * 8, \
             &ksrc[((size_t)b * NN + (M1) + key) * 32 + dseg * 4]); \
    } \
    _Pragma("unroll") \
    for (int i = 0; i < 4; i++) { \
        int idx = tid + i * NT; \
        int vl  = idx >> 10; \
        int r2  = idx & 1023; \
        int ch  = r2 >> 2, kq = r2 & 3; \
        int kqs = kq ^ ((ch >> 1) & 3); \
        const __nv_bfloat16* vsrc = vl ? vv_l : vv_h; \
        cpa16(sb + VS_OFF + ((BUF) * 2 + vl) * 16384 + ch * 64 + kqs * 16, \
              &vsrc[((size_t)b * NC + ch) * NN + (M1) + kq * 8]); \
    } \
    CP_COMMIT(); \
} while (0)

    LOAD_TILE(0, 0);
    LOAD_TILE(1, TK);
    CP_WAIT0();
    __syncthreads();

    // ---- hoist Q A-fragments via direct LDS.32 ----
    uint32_t QH[2][4], QL[2][4];
    {
        const char* q0 = smem + QS_OFF + (mg * 16 + lq) * 80;
        const char* q8 = q0 + 8 * 80;
#pragma unroll
        for (int ks = 0; ks < 2; ks++) {
            int d0 = (ks * 16 + 2 * lr) * 2;   // byte offset, 4B aligned
            QH[ks][0] = *(const uint32_t*)(q0 + d0);
            QH[ks][1] = *(const uint32_t*)(q8 + d0);
            QH[ks][2] = *(const uint32_t*)(q0 + d0 + 16);
            QH[ks][3] = *(const uint32_t*)(q8 + d0 + 16);
            QL[ks][0] = *(const uint32_t*)(q0 + QL_REL + d0);
            QL[ks][1] = *(const uint32_t*)(q8 + QL_REL + d0);
            QL[ks][2] = *(const uint32_t*)(q0 + QL_REL + d0 + 16);
            QL[ks][3] = *(const uint32_t*)(q8 + QL_REL + d0 + 16);
        }
    }

    float O[16][4];
#pragma unroll
    for (int i = 0; i < 16; i++)
#pragma unroll
        for (int j = 0; j < 4; j++) O[i][j] = 0.f;
    float lsum0 = 0.f, lsum1 = 0.f;

    // ---- per-tile compute: QK both kgs, batched exp/pack, then both PVs ----
    auto compute_tile = [&](int buf) {
        const char* kbh = smem + KS_OFF + buf * 5120;    // hi limb
        const char* kbl = kbh + 2560;                    // lo limb
        const int db = 4 * lr;

        float ea0[4] = {0,0,0,0}, ea1[4] = {0,0,0,0};    // kg0
        float eb0[4] = {0,0,0,0}, eb1[4] = {0,0,0,0};    // kg1

        // ---- QK kg0 (K frags scope-local, die before kg1 load) ----
        {
            const int r0 = lq * 80;
            const int r8 = r0 + 640;
            uint32_t kh[8], kl[8];
            kh[0] = *(const uint32_t*)(kbh + r0 + db);
            kh[1] = *(const uint32_t*)(kbh + r0 + db + 16);
            kh[2] = *(const uint32_t*)(kbh + r0 + db + 32);
            kh[3] = *(const uint32_t*)(kbh + r0 + db + 48);
            kh[4] = *(const uint32_t*)(kbh + r8 + db);
            kh[5] = *(const uint32_t*)(kbh + r8 + db + 16);
            kh[6] = *(const uint32_t*)(kbh + r8 + db + 32);
            kh[7] = *(const uint32_t*)(kbh + r8 + db + 48);
            kl[0] = *(const uint32_t*)(kbl + r0 + db);
            kl[1] = *(const uint32_t*)(kbl + r0 + db + 16);
            kl[2] = *(const uint32_t*)(kbl + r0 + db + 32);
            kl[3] = *(const uint32_t*)(kbl + r0 + db + 48);
            kl[4] = *(const uint32_t*)(kbl + r8 + db);
            kl[5] = *(const uint32_t*)(kbl + r8 + db + 16);
            kl[6] = *(const uint32_t*)(kbl + r8 + db + 32);
            kl[7] = *(const uint32_t*)(kbl + r8 + db + 48);
            mma_bf16(ea0, QH[0], kh[0], kh[1]);
            mma_bf16(ea0, QH[1], kh[2], kh[3]);
            mma_bf16(ea1, QH[0], kh[4], kh[5]);
            mma_bf16(ea1, QH[1], kh[6], kh[7]);
            mma_bf16(ea0, QL[0], kh[0], kh[1]);
            mma_bf16(ea0, QL[1], kh[2], kh[3]);
            mma_bf16(ea1, QL[0], kh[4], kh[5]);
            mma_bf16(ea1, QL[1], kh[6], kh[7]);
            mma_bf16(ea0, QH[0], kl[0], kl[1]);
            mma_bf16(ea0, QH[1], kl[2], kl[3]);
            mma_bf16(ea1, QH[0], kl[4], kl[5]);
            mma_bf16(ea1, QH[1], kl[6], kl[7]);
        }
        // ---- QK kg1 ----
        {
            const int r0 = (16 + lq) * 80;
            const int r8 = r0 + 640;
            uint32_t kh[8], kl[8];
            kh[0] = *(const uint32_t*)(kbh + r0 + db);
            kh[1] = *(const uint32_t*)(kbh + r0 + db + 16);
            kh[2] = *(const uint32_t*)(kbh + r0 + db + 32);
            kh[3] = *(const uint32_t*)(kbh + r0 + db + 48);
            kh[4] = *(const uint32_t*)(kbh + r8 + db);
            kh[5] = *(const uint32_t*)(kbh + r8 + db + 16);
            kh[6] = *(const uint32_t*)(kbh + r8 + db + 32);
            kh[7] = *(const uint32_t*)(kbh + r8 + db + 48);
            kl[0] = *(const uint32_t*)(kbl + r0 + db);
            kl[1] = *(const uint32_t*)(kbl + r0 + db + 16);
            kl[2] = *(const uint32_t*)(kbl + r0 + db + 32);
            kl[3] = *(const uint32_t*)(kbl + r0 + db + 48);
            kl[4] = *(const uint32_t*)(kbl + r8 + db);
            kl[5] = *(const uint32_t*)(kbl + r8 + db + 16);
            kl[6] = *(const uint32_t*)(kbl + r8 + db + 32);
            kl[7] = *(const uint32_t*)(kbl + r8 + db + 48);
            mma_bf16(eb0, QH[0], kh[0], kh[1]);
            mma_bf16(eb0, QH[1], kh[2], kh[3]);
            mma_bf16(eb1, QH[0], kh[4], kh[5]);
            mma_bf16(eb1, QH[1], kh[6], kh[7]);
            mma_bf16(eb0, QL[0], kh[0], kh[1]);
            mma_bf16(eb0, QL[1], kh[2], kh[3]);
            mma_bf16(eb1, QL[0], kh[4], kh[5]);
            mma_bf16(eb1, QL[1], kh[6], kh[7]);
            mma_bf16(eb0, QH[0], kl[0], kl[1]);
            mma_bf16(eb0, QH[1], kl[2], kl[3]);
            mma_bf16(eb1, QH[0], kl[4], kl[5]);
            mma_bf16(eb1, QH[1], kl[6], kl[7]);
        }

        // ---- batched softmax numerators + bf16 split P fragments ----
        uint32_t PH[2][4], PL[2][4];
        {
            // kg0 (same value/order as R14's kg0 block)
            float p00 = __expf(ea0[0]), p01 = __expf(ea0[1]);
            float p02 = __expf(ea0[2]), p03 = __expf(ea0[3]);
            float p10 = __expf(ea1[0]), p11 = __expf(ea1[1]);
            float p12 = __expf(ea1[2]), p13 = __expf(ea1[3]);
            lsum0 += p00 + p01 + p10 + p11;
            lsum1 += p02 + p03 + p12 + p13;
            float h0, h1;
            h0 = bfh(p00); h1 = bfh(p01);
            PH[0][0] = bf2pack(h0, h1); PL[0][0] = bf2pack(p00 - h0, p01 - h1);
            h0 = bfh(p02); h1 = bfh(p03);
            PH[0][1] = bf2pack(h0, h1); PL[0][1] = bf2pack(p02 - h0, p03 - h1);
            h0 = bfh(p10); h1 = bfh(p11);
            PH[0][2] = bf2pack(h0, h1); PL[0][2] = bf2pack(p10 - h0, p11 - h1);
            h0 = bfh(p12); h1 = bfh(p13);
            PH[0][3] = bf2pack(h0, h1); PL[0][3] = bf2pack(p12 - h0, p13 - h1);
        }
        {
            // kg1
            float p00 = __expf(eb0[0]), p01 = __expf(eb0[1]);
            float p02 = __expf(eb0[2]), p03 = __expf(eb0[3]);
            float p10 = __expf(eb1[0]), p11 = __expf(eb1[1]);
            float p12 = __expf(eb1[2]), p13 = __expf(eb1[3]);
            lsum0 += p00 + p01 + p10 + p11;
            lsum1 += p02 + p03 + p12 + p13;
            float h0, h1;
            h0 = bfh(p00); h1 = bfh(p01);
            PH[1][0] = bf2pack(h0, h1); PL[1][0] = bf2pack(p00 - h0, p01 - h1);
            h0 = bfh(p02); h1 = bfh(p03);
            PH[1][1] = bf2pack(h0, h1); PL[1][1] = bf2pack(p02 - h0, p03 - h1);
            h0 = bfh(p10); h1 = bfh(p11);
            PH[1][2] = bf2pack(h0, h1); PL[1][2] = bf2pack(p10 - h0, p11 - h1);
            h0 = bfh(p12); h1 = bfh(p13);
            PH[1][3] = bf2pack(h0, h1); PL[1][3] = bf2pack(p12 - h0, p13 - h1);
        }

        // ---- PV kg0 then kg1 (same per-O accumulation order as R14) ----
        const int chL = cg * 128 + ((g >> 1) << 3) + gr;
#pragma unroll
        for (int kg = 0; kg < 2; kg++) {
            const int kblk = kg * 2 + (g & 1);
#pragma unroll
            for (int np = 0; np < 8; np++) {
                int ch = chL + np * 16;
                uint32_t row_off = (uint32_t)(ch * 64 + ((kblk ^ ((ch >> 1) & 3)) * 16));
                uint32_t ah = sb + VS_OFF + (buf * 2 + 0) * 16384 + row_off;
                uint32_t al = sb + VS_OFF + (buf * 2 + 1) * 16384 + row_off;
                uint32_t vh[4], vl[4];
                ldsm4(vh, ah);
                ldsm4(vl, al);
#pragma unroll
                for (int u = 0; u < 2; u++) {
                    float* o = O[np * 2 + u];
                    mma_bf16(o, PH[kg], vh[2*u], vh[2*u + 1]);
                    mma_bf16(o, PH[kg], vl[2*u], vl[2*u + 1]);
                    mma_bf16(o, PL[kg], vh[2*u], vh[2*u + 1]);
                }
            }
        }
    };

    // ---- main loop: pairs of tiles, one wait+barrier per pair ----
    for (int t = 0; t < NN / TK; t += 2) {
        if (t + 2 < NN / TK) LOAD_TILE((t + 2) & 3, (t + 2) * TK);
        if (t + 3 < NN / TK) LOAD_TILE((t + 3) & 3, (t + 3) * TK);
        compute_tile(t & 3);
        compute_tile((t + 1) & 3);
        CP_WAIT0();
        __syncthreads();
    }

    // ---- row-sum reduce over lane quads ----
    lsum0 += __shfl_xor_sync(0xffffffffu, lsum0, 1);
    lsum0 += __shfl_xor_sync(0xffffffffu, lsum0, 2);
    lsum1 += __shfl_xor_sync(0xffffffffu, lsum1, 1);
    lsum1 += __shfl_xor_sync(0xffffffffu, lsum1, 2);
    const float inv0 = 1.0f / lsum0;
    const float inv1 = 1.0f / lsum1;
    const float gm = __ldg(gamma);

    // ---- epilogue: two 64-row passes through [256][68] f32 staging ----
    float* stg = (float*)smem;
#pragma unroll
    for (int half = 0; half < 2; half++) {
        __syncthreads();
        if ((mg >> 2) == half) {
#pragma unroll
            for (int oc = 0; oc < 16; oc++) {
                int ch = cg * 128 + oc * 8 + lr * 2;
                int r0 = mg * 16 + lq - half * 64, r1 = r0 + 8;
                float o0 = O[oc][0] * inv0, o1 = O[oc][1] * inv0;
                float o2 = O[oc][2] * inv1, o3 = O[oc][3] * inv1;
                stg[ ch      * 68 + r0] = floorf((gm * o0 + o0) * 256.f) * 0.00390625f;
                stg[(ch + 1) * 68 + r0] = floorf((gm * o1 + o1) * 256.f) * 0.00390625f;
                stg[ ch      * 68 + r1] = floorf((gm * o2 + o2) * 256.f) * 0.00390625f;
                stg[(ch + 1) * 68 + r1] = floorf((gm * o3 + o3) * 256.f) * 0.00390625f;
            }
        }
        __syncthreads();
#pragma unroll
        for (int i = 0; i < 8; i++) {
            int ch = (tid >> 4) + i * 32;
            int r4 = (tid & 15) * 4;
            *(float4*)&out[((size_t)b * NC + ch) * NN + n0 + half * 64 + r4] =
                *(float4*)&stg[ch * 68 + r4];
        }
    }
}

// ---------------- launch ----------------
extern "C" void kernel_launch(void* const* d_in, const int* in_sizes, int n_in,
                              void* d_out, int out_size)
{
    const float* x     = (const float*)d_in[0];
    const float* wq    = (const float*)d_in[1];
    const float* bq    = (const float*)d_in[2];
    const float* wk    = (const float*)d_in[3];
    const float* bk    = (const float*)d_in[4];
    const float* wv    = (const float*)d_in[5];
    const float* bv    = (const float*)d_in[6];
    const float* gamma = (const float*)d_in[7];
    float* out = (float*)d_out;

    dim3 gp(NN / 256, 10, NB);
    proj_kernel<<<gp, 256>>>(x, wq, bq, wk, bk, wv, bv);

    cudaFuncSetAttribute(attn_kernel, cudaFuncAttributeMaxDynamicSharedMemorySize, SMEM_BYTES);
    dim3 ga(NN / MR, NB);
    attn_kernel<<<ga, NT, SMEM_BYTES>>>(out, gamma);
}

// round 16
// speedup vs baseline: 1.0370x; 1.0370x over previous
#include <cuda_runtime.h>
#include <cuda_bf16.h>
#include <cstdint>

#define NB  8
#define NC  256
#define NN  4096
#define MR  128     // query rows per CTA
#define TK  32      // keys per gmem tile
#define NT  512     // threads per CTA

// ---------------- scratch (no allocs allowed) ----------------
__device__ alignas(16) __nv_bfloat16 qth[NB * NN * 32];  // [b][n][d] bf16 hi
__device__ alignas(16) __nv_bfloat16 qtl[NB * NN * 32];  // residual
__device__ alignas(16) __nv_bfloat16 kth[NB * NN * 32];
__device__ alignas(16) __nv_bfloat16 ktl[NB * NN * 32];
__device__ alignas(16) __nv_bfloat16 vv_h[NB * NC * NN]; // [b][ch][n] bf16-hi
__device__ alignas(16) __nv_bfloat16 vv_l[NB * NC * NN]; // bf16 residual

// ---------------- helpers ----------------
__device__ __forceinline__ uint32_t smem_u32(const void* p) {
    uint32_t a;
    asm("{ .reg .u64 t; cvta.to.shared.u64 t, %1; cvt.u32.u64 %0, t; }" : "=r"(a) : "l"(p));
    return a;
}
__device__ __forceinline__ uint32_t bf2pack(float lo, float hi) {
    uint32_t r;
    asm("cvt.rn.bf16x2.f32 %0, %1, %2;" : "=r"(r) : "f"(hi), "f"(lo));
    return r;
}
__device__ __forceinline__ float bfh(float x) {
    return __bfloat162float(__float2bfloat16(x));
}
__device__ __forceinline__ unsigned long long pack2(float a, float b) {
    unsigned long long r;
    asm("mov.b64 %0, {%1, %2};" : "=l"(r) : "f"(a), "f"(b));
    return r;
}
__device__ __forceinline__ void fma2(unsigned long long& d, unsigned long long a, unsigned long long b) {
    asm("fma.rn.f32x2 %0, %1, %2, %0;" : "+l"(d) : "l"(a), "l"(b));
}
__device__ __forceinline__ float2 unpack2(unsigned long long v) {
    float lo, hi;
    asm("mov.b64 {%0, %1}, %2;" : "=f"(lo), "=f"(hi) : "l"(v));
    return make_float2(lo, hi);
}
__device__ __forceinline__ void mma_bf16(float* c, const uint32_t* a,
                                         uint32_t b0, uint32_t b1) {
    asm volatile(
        "mma.sync.aligned.m16n8k16.row.col.f32.bf16.bf16.f32 "
        "{%0,%1,%2,%3},{%4,%5,%6,%7},{%8,%9},{%0,%1,%2,%3};"
        : "+f"(c[0]), "+f"(c[1]), "+f"(c[2]), "+f"(c[3])
        : "r"(a[0]), "r"(a[1]), "r"(a[2]), "r"(a[3]), "r"(b0), "r"(b1));
}
// Validated helper: NON-trans ldmatrix.
__device__ __forceinline__ void ldsm4(uint32_t* r, uint32_t addr) {
    asm volatile("ldmatrix.sync.aligned.m8n8.x4.shared.b16 {%0,%1,%2,%3},[%4];"
                 : "=r"(r[0]), "=r"(r[1]), "=r"(r[2]), "=r"(r[3]) : "r"(addr));
}
__device__ __forceinline__ void cpa16(uint32_t dst, const void* src) {
    asm volatile("cp.async.cg.shared.global [%0], [%1], 16;" :: "r"(dst), "l"(src));
}
__device__ __forceinline__ void cpa8(uint32_t dst, const void* src) {
    asm volatile("cp.async.ca.shared.global [%0], [%1], 8;" :: "r"(dst), "l"(src));
}
#define CP_COMMIT() asm volatile("cp.async.commit_group;" ::: "memory")
#define CP_WAIT0()  asm volatile("cp.async.wait_group 0;" ::: "memory")

// ---------------- projection kernel (R14 body, 3 CTAs/SM reg cap) -----------
__global__ void __launch_bounds__(256, 3) proj_kernel(
    const float* __restrict__ x,
    const float* __restrict__ wq, const float* __restrict__ bq,
    const float* __restrict__ wk, const float* __restrict__ bk,
    const float* __restrict__ wv, const float* __restrict__ bv)
{
    __shared__ float xs[32][256];
    __shared__ unsigned long long ws2[32][34];   // [c][o] duplicated (w,w) pairs

    const int b  = blockIdx.z;
    const int n0 = blockIdx.x * 256;
    const int o0 = blockIdx.y * 32;
    const int tid = threadIdx.x;
    const int tx = tid & 63;
    const int ty = tid >> 6;

    unsigned long long accp[8][2];
#pragma unroll
    for (int i = 0; i < 8; i++) { accp[i][0] = 0ull; accp[i][1] = 0ull; }

    for (int cc = 0; cc < NC; cc += 32) {
        __syncthreads();
#pragma unroll
        for (int p = 0; p < 8; p++) {
            int idx = tid + p * 256;
            int c  = idx >> 6;
            int n4 = idx & 63;
            *(float4*)&xs[c][n4 * 4] =
                *(const float4*)&x[(size_t)(b * NC + cc + c) * NN + n0 + n4 * 4];
        }
#pragma unroll
        for (int p = 0; p < 4; p++) {
            int idx = tid + p * 256;
            int o  = idx >> 5;
            int c2 = idx & 31;
            int og = o0 + o;
            const float* wsrc;
            if (og < 32)        wsrc = wq + og * NC;
            else if (og < 64)   wsrc = wk + (og - 32) * NC;
            else                wsrc = wv + (og - 64) * NC;
            float v = wsrc[cc + c2];
            ws2[c2][o] = pack2(v, v);
        }
        __syncthreads();
#pragma unroll
        for (int c = 0; c < 32; c++) {
            ulonglong2 xp = *(const ulonglong2*)&xs[c][tx * 4];
            ulonglong2 wa = *(const ulonglong2*)&ws2[c][ty * 8];
            ulonglong2 wb = *(const ulonglong2*)&ws2[c][ty * 8 + 2];
            ulonglong2 wc = *(const ulonglong2*)&ws2[c][ty * 8 + 4];
            ulonglong2 wd = *(const ulonglong2*)&ws2[c][ty * 8 + 6];
            fma2(accp[0][0], wa.x, xp.x); fma2(accp[0][1], wa.x, xp.y);
            fma2(accp[1][0], wa.y, xp.x); fma2(accp[1][1], wa.y, xp.y);
            fma2(accp[2][0], wb.x, xp.x); fma2(accp[2][1], wb.x, xp.y);
            fma2(accp[3][0], wb.y, xp.x); fma2(accp[3][1], wb.y, xp.y);
            fma2(accp[4][0], wc.x, xp.x); fma2(accp[4][1], wc.x, xp.y);
            fma2(accp[5][0], wc.y, xp.x); fma2(accp[5][1], wc.y, xp.y);
            fma2(accp[6][0], wd.x, xp.x); fma2(accp[6][1], wd.x, xp.y);
            fma2(accp[7][0], wd.y, xp.x); fma2(accp[7][1], wd.y, xp.y);
        }
    }

    float acc[8][4];
#pragma unroll
    for (int i = 0; i < 8; i++) {
        float2 f0 = unpack2(accp[i][0]);
        float2 f1 = unpack2(accp[i][1]);
        acc[i][0] = f0.x; acc[i][1] = f0.y; acc[i][2] = f1.x; acc[i][3] = f1.y;
    }

    if (o0 < 64) {
        const float* bias = (o0 == 0) ? bq : bk;
        __syncthreads();
#pragma unroll
        for (int i = 0; i < 8; i++) {
            int o = ty * 8 + i;
            float bs = bias[o];
#pragma unroll
            for (int j = 0; j < 4; j++)
                xs[o][tx * 4 + j] = acc[i][j] + bs;
        }
        __syncthreads();
        const int n = tid;
        uint32_t hi[16], lo[16];
#pragma unroll
        for (int d2 = 0; d2 < 16; d2++) {
            float v0 = xs[2 * d2][n], v1 = xs[2 * d2 + 1][n];
            float h0 = bfh(v0), h1 = bfh(v1);
            hi[d2] = bf2pack(h0, h1);
            lo[d2] = bf2pack(v0 - h0, v1 - h1);
        }
        __nv_bfloat16* dh = ((o0 == 0) ? qth : kth) + ((size_t)b * NN + n0 + n) * 32;
        __nv_bfloat16* dl = ((o0 == 0) ? qtl : ktl) + ((size_t)b * NN + n0 + n) * 32;
#pragma unroll
        for (int q4 = 0; q4 < 4; q4++) {
            *(uint4*)&dh[q4 * 8] = ((const uint4*)hi)[q4];
            *(uint4*)&dl[q4 * 8] = ((const uint4*)lo)[q4];
        }
    } else {
#pragma unroll
        for (int i = 0; i < 8; i++) {
            int ch = o0 - 64 + ty * 8 + i;
            float bs = bv[ch];
            float vals[4] = {acc[i][0]+bs, acc[i][1]+bs, acc[i][2]+bs, acc[i][3]+bs};
            uint32_t hp[2], lp[2];
#pragma unroll
            for (int p = 0; p < 2; p++) {
                float h0 = bfh(vals[2*p]), h1 = bfh(vals[2*p+1]);
                hp[p] = bf2pack(h0, h1);
                lp[p] = bf2pack(vals[2*p] - h0, vals[2*p+1] - h1);
            }
            size_t off = ((size_t)b * NC + ch) * NN + n0 + tx * 4;
            *(uint32_t*)&vv_h[off]     = hp[0];
            *(uint32_t*)&vv_h[off + 2] = hp[1];
            *(uint32_t*)&vv_l[off]     = lp[0];
            *(uint32_t*)&vv_l[off + 2] = lp[1];
        }
    }
}

// ---------------- fused attention kernel (byte-identical to R14) ------------
// smem bytes:
//   [0,     20480)  Q stage  bf16 [2 limb][128 rows][40] (80B row stride)
//   [20480, 40960)  K tiles  bf16 [4 buf][2 limb][32 keys][40]
//   [40960, 172032) V tiles  bf16 [4 buf][2 limb][256 ch][32] (period-8 swizzle)
//   epilogue staging [256][68] f32 reuses [0, 69632)
#define QS_OFF 0
#define QL_REL 10240
#define KS_OFF 20480
#define VS_OFF 40960
#define SMEM_BYTES 172032

__global__ void __launch_bounds__(NT, 1) attn_kernel(float* __restrict__ out,
                                                     const float* __restrict__ gamma)
{
    extern __shared__ char smem[];
    const uint32_t sb = smem_u32(smem);

    const int b    = blockIdx.y;
    const int n0   = blockIdx.x * MR;
    const int tid  = threadIdx.x;
    const int w    = tid >> 5;
    const int lane = tid & 31;
    const int mg   = w >> 1;          // row group 0..7 (16 rows each)
    const int cg   = w & 1;           // channel group 0..1 (128 ch each)
    const int lq   = lane >> 2;       // lane/4
    const int lr   = lane & 3;        // lane%4
    const int g    = lane >> 3;       // ldmatrix group
    const int gr   = lane & 7;

    // ---- stage Q (both limbs): 128 rows x 4 segs, one per thread ----
    {
        int row = tid >> 2, seg = tid & 3;
        size_t go = ((size_t)b * NN + n0 + row) * 32 + seg * 8;
        *(uint4*)(smem + QS_OFF +          row * 80 + seg * 16) = *(const uint4*)&qth[go];
        *(uint4*)(smem + QS_OFF + QL_REL + row * 80 + seg * 16) = *(const uint4*)&qtl[go];
    }

    // ---- async tile loads; V swizzle period-8: kqs = kq ^ ((ch>>1)&3) ----
#define LOAD_TILE(BUF, M1) do { \
    { \
        int limb = tid >> 8; \
        int rem  = tid & 255; \
        int key  = rem >> 3, dseg = rem & 7; \
        const __nv_bfloat16* ksrc = limb ? ktl : kth; \
        cpa8(sb + KS_OFF + (BUF) * 5120 + limb * 2560 + key * 80 + dseg * 8, \
             &ksrc[((size_t)b * NN + (M1) + key) * 32 + dseg * 4]); \
    } \
    _Pragma("unroll") \
    for (int i = 0; i < 4; i++) { \
        int idx = tid + i * NT; \
        int vl  = idx >> 10; \
        int r2  = idx & 1023; \
        int ch  = r2 >> 2, kq = r2 & 3; \
        int kqs = kq ^ ((ch >> 1) & 3); \
        const __nv_bfloat16* vsrc = vl ? vv_l : vv_h; \
        cpa16(sb + VS_OFF + ((BUF) * 2 + vl) * 16384 + ch * 64 + kqs * 16, \
              &vsrc[((size_t)b * NC + ch) * NN + (M1) + kq * 8]); \
    } \
    CP_COMMIT(); \
} while (0)

    LOAD_TILE(0, 0);
    LOAD_TILE(1, TK);
    CP_WAIT0();
    __syncthreads();

    // ---- hoist Q A-fragments via direct LDS.32 ----
    uint32_t QH[2][4], QL[2][4];
    {
        const char* q0 = smem + QS_OFF + (mg * 16 + lq) * 80;
        const char* q8 = q0 + 8 * 80;
#pragma unroll
        for (int ks = 0; ks < 2; ks++) {
            int d0 = (ks * 16 + 2 * lr) * 2;   // byte offset, 4B aligned
            QH[ks][0] = *(const uint32_t*)(q0 + d0);
            QH[ks][1] = *(const uint32_t*)(q8 + d0);
            QH[ks][2] = *(const uint32_t*)(q0 + d0 + 16);
            QH[ks][3] = *(const uint32_t*)(q8 + d0 + 16);
            QL[ks][0] = *(const uint32_t*)(q0 + QL_REL + d0);
            QL[ks][1] = *(const uint32_t*)(q8 + QL_REL + d0);
            QL[ks][2] = *(const uint32_t*)(q0 + QL_REL + d0 + 16);
            QL[ks][3] = *(const uint32_t*)(q8 + QL_REL + d0 + 16);
        }
    }

    float O[16][4];
#pragma unroll
    for (int i = 0; i < 16; i++)
#pragma unroll
        for (int j = 0; j < 4; j++) O[i][j] = 0.f;
    float lsum0 = 0.f, lsum1 = 0.f;

    // ---- per-tile compute (R14 structure: per-kg K-load+QK+exp+pack+PV) ----
    auto compute_tile = [&](int buf) {
#pragma unroll
        for (int kg = 0; kg < 2; kg++) {          // two 16-key groups
            // ---- K B-fragments via direct LDS.32 ----
            const char* kbh = smem + KS_OFF + buf * 5120;    // hi limb
            const char* kbl = kbh + 2560;                    // lo limb
            const int r0 = (kg * 16 + lq) * 80;              // keys n=lq (0-7)
            const int r8 = r0 + 640;                         // keys 8-15
            const int db = 4 * lr;
            uint32_t kh[8], kl[8];
            kh[0] = *(const uint32_t*)(kbh + r0 + db);
            kh[1] = *(const uint32_t*)(kbh + r0 + db + 16);
            kh[2] = *(const uint32_t*)(kbh + r0 + db + 32);
            kh[3] = *(const uint32_t*)(kbh + r0 + db + 48);
            kh[4] = *(const uint32_t*)(kbh + r8 + db);
            kh[5] = *(const uint32_t*)(kbh + r8 + db + 16);
            kh[6] = *(const uint32_t*)(kbh + r8 + db + 32);
            kh[7] = *(const uint32_t*)(kbh + r8 + db + 48);
            kl[0] = *(const uint32_t*)(kbl + r0 + db);
            kl[1] = *(const uint32_t*)(kbl + r0 + db + 16);
            kl[2] = *(const uint32_t*)(kbl + r0 + db + 32);
            kl[3] = *(const uint32_t*)(kbl + r0 + db + 48);
            kl[4] = *(const uint32_t*)(kbl + r8 + db);
            kl[5] = *(const uint32_t*)(kbl + r8 + db + 16);
            kl[6] = *(const uint32_t*)(kbl + r8 + db + 32);
            kl[7] = *(const uint32_t*)(kbl + r8 + db + 48);

            float e0[4] = {0,0,0,0}, e1[4] = {0,0,0,0};
            // hh
            mma_bf16(e0, QH[0], kh[0], kh[1]);
            mma_bf16(e0, QH[1], kh[2], kh[3]);
            mma_bf16(e1, QH[0], kh[4], kh[5]);
            mma_bf16(e1, QH[1], kh[6], kh[7]);
            // lh (Q lo x K hi)
            mma_bf16(e0, QL[0], kh[0], kh[1]);
            mma_bf16(e0, QL[1], kh[2], kh[3]);
            mma_bf16(e1, QL[0], kh[4], kh[5]);
            mma_bf16(e1, QL[1], kh[6], kh[7]);
            // hl (Q hi x K lo)
            mma_bf16(e0, QH[0], kl[0], kl[1]);
            mma_bf16(e0, QH[1], kl[2], kl[3]);
            mma_bf16(e1, QH[0], kl[4], kl[5]);
            mma_bf16(e1, QH[1], kl[6], kl[7]);

            // ---- softmax numerators + bf16 split P fragments ----
            float p00 = __expf(e0[0]), p01 = __expf(e0[1]);
            float p02 = __expf(e0[2]), p03 = __expf(e0[3]);
            float p10 = __expf(e1[0]), p11 = __expf(e1[1]);
            float p12 = __expf(e1[2]), p13 = __expf(e1[3]);
            lsum0 += p00 + p01 + p10 + p11;
            lsum1 += p02 + p03 + p12 + p13;

            uint32_t PH[4], PL[4];
            {
                float h0, h1;
                h0 = bfh(p00); h1 = bfh(p01);
                PH[0] = bf2pack(h0, h1); PL[0] = bf2pack(p00 - h0, p01 - h1);
                h0 = bfh(p02); h1 = bfh(p03);
                PH[1] = bf2pack(h0, h1); PL[1] = bf2pack(p02 - h0, p03 - h1);
                h0 = bfh(p10); h1 = bfh(p11);
                PH[2] = bf2pack(h0, h1); PL[2] = bf2pack(p10 - h0, p11 - h1);
                h0 = bfh(p12); h1 = bfh(p13);
                PH[3] = bf2pack(h0, h1); PL[3] = bf2pack(p12 - h0, p13 - h1);
            }

            // ---- PV: bf16x2 over 128 channels (period-8 swizzle read) ----
            const int chL  = cg * 128 + ((g >> 1) << 3) + gr;   // + np*16
            const int kblk = kg * 2 + (g & 1);
#pragma unroll
            for (int np = 0; np < 8; np++) {
                int ch = chL + np * 16;
                uint32_t row_off = (uint32_t)(ch * 64 + ((kblk ^ ((ch >> 1) & 3)) * 16));
                uint32_t ah = sb + VS_OFF + (buf * 2 + 0) * 16384 + row_off;
                uint32_t al = sb + VS_OFF + (buf * 2 + 1) * 16384 + row_off;
                uint32_t vh[4], vl[4];
                ldsm4(vh, ah);
                ldsm4(vl, al);
#pragma unroll
                for (int u = 0; u < 2; u++) {
                    float* o = O[np * 2 + u];
                    mma_bf16(o, PH, vh[2*u], vh[2*u + 1]);
                    mma_bf16(o, PH, vl[2*u], vl[2*u + 1]);
                    mma_bf16(o, PL, vh[2*u], vh[2*u + 1]);
                }
            }
        }
    };

    // ---- main loop: pairs of tiles, one wait+barrier per pair ----
    for (int t = 0; t < NN / TK; t += 2) {
        if (t + 2 < NN / TK) LOAD_TILE((t + 2) & 3, (t + 2) * TK);
        if (t + 3 < NN / TK) LOAD_TILE((t + 3) & 3, (t + 3) * TK);
        compute_tile(t & 3);
        compute_tile((t + 1) & 3);
        CP_WAIT0();
        __syncthreads();
    }

    // ---- row-sum reduce over lane quads ----
    lsum0 += __shfl_xor_sync(0xffffffffu, lsum0, 1);
    lsum0 += __shfl_xor_sync(0xffffffffu, lsum0, 2);
    lsum1 += __shfl_xor_sync(0xffffffffu, lsum1, 1);
    lsum1 += __shfl_xor_sync(0xffffffffu, lsum1, 2);
    const float inv0 = 1.0f / lsum0;
    const float inv1 = 1.0f / lsum1;
    const float gm = __ldg(gamma);

    // ---- epilogue: two 64-row passes through [256][68] f32 staging ----
    float* stg = (float*)smem;
#pragma unroll
    for (int half = 0; half < 2; half++) {
        __syncthreads();
        if ((mg >> 2) == half) {
#pragma unroll
            for (int oc = 0; oc < 16; oc++) {
                int ch = cg * 128 + oc * 8 + lr * 2;
                int r0 = mg * 16 + lq - half * 64, r1 = r0 + 8;
                float o0 = O[oc][0] * inv0, o1 = O[oc][1] * inv0;
                float o2 = O[oc][2] * inv1, o3 = O[oc][3] * inv1;
                stg[ ch      * 68 + r0] = floorf((gm * o0 + o0) * 256.f) * 0.00390625f;
                stg[(ch + 1) * 68 + r0] = floorf((gm * o1 + o1) * 256.f) * 0.00390625f;
                stg[ ch      * 68 + r1] = floorf((gm * o2 + o2) * 256.f) * 0.00390625f;
                stg[(ch + 1) * 68 + r1] = floorf((gm * o3 + o3) * 256.f) * 0.00390625f;
            }
        }
        __syncthreads();
#pragma unroll
        for (int i = 0; i < 8; i++) {
            int ch = (tid >> 4) + i * 32;
            int r4 = (tid & 15) * 4;
            *(float4*)&out[((size_t)b * NC + ch) * NN + n0 + half * 64 + r4] =
                *(float4*)&stg[ch * 68 + r4];
        }
    }
}

// ---------------- launch ----------------
extern "C" void kernel_launch(void* const* d_in, const int* in_sizes, int n_in,
                              void* d_out, int out_size)
{
    const float* x     = (const float*)d_in[0];
    const float* wq    = (const float*)d_in[1];
    const float* bq    = (const float*)d_in[2];
    const float* wk    = (const float*)d_in[3];
    const float* bk    = (const float*)d_in[4];
    const float* wv    = (const float*)d_in[5];
    const float* bv    = (const float*)d_in[6];
    const float* gamma = (const float*)d_in[7];
    float* out = (float*)d_out;

    dim3 gp(NN / 256, 10, NB);
    proj_kernel<<<gp, 256>>>(x, wq, bq, wk, bk, wv, bv);

    cudaFuncSetAttribute(attn_kernel, cudaFuncAttributeMaxDynamicSharedMemorySize, SMEM_BYTES);
    dim3 ga(NN / MR, NB);
    attn_kernel<<<ga, NT, SMEM_BYTES>>>(out, gamma);
}

// round 17
// speedup vs baseline: 1.1502x; 1.1092x over previous
#include <cuda_runtime.h>
#include <cuda_bf16.h>
#include <cstdint>

#define NB  8
#define NC  256
#define NN  4096
#define MR  128     // query rows per CTA
#define TK  32      // keys per gmem tile
#define NT  512     // threads per CTA

// ---------------- scratch (no allocs allowed) ----------------
__device__ alignas(16) __nv_bfloat16 qth[NB * NN * 32];  // [b][n][d] bf16 hi
__device__ alignas(16) __nv_bfloat16 qtl[NB * NN * 32];  // residual
__device__ alignas(16) __nv_bfloat16 kth[NB * NN * 32];
__device__ alignas(16) __nv_bfloat16 ktl[NB * NN * 32];
__device__ alignas(16) __nv_bfloat16 vv_h[NB * NC * NN]; // [b][ch][n] bf16-hi
__device__ alignas(16) __nv_bfloat16 vv_l[NB * NC * NN]; // bf16 residual

// ---------------- helpers ----------------
__device__ __forceinline__ uint32_t smem_u32(const void* p) {
    uint32_t a;
    asm("{ .reg .u64 t; cvta.to.shared.u64 t, %1; cvt.u32.u64 %0, t; }" : "=r"(a) : "l"(p));
    return a;
}
__device__ __forceinline__ uint32_t bf2pack(float lo, float hi) {
    uint32_t r;
    asm("cvt.rn.bf16x2.f32 %0, %1, %2;" : "=r"(r) : "f"(hi), "f"(lo));
    return r;
}
__device__ __forceinline__ float bfh(float x) {
    return __bfloat162float(__float2bfloat16(x));
}
__device__ __forceinline__ unsigned long long pack2(float a, float b) {
    unsigned long long r;
    asm("mov.b64 %0, {%1, %2};" : "=l"(r) : "f"(a), "f"(b));
    return r;
}
__device__ __forceinline__ void fma2(unsigned long long& d, unsigned long long a, unsigned long long b) {
    asm("fma.rn.f32x2 %0, %1, %2, %0;" : "+l"(d) : "l"(a), "l"(b));
}
__device__ __forceinline__ float2 unpack2(unsigned long long v) {
    float lo, hi;
    asm("mov.b64 {%0, %1}, %2;" : "=f"(lo), "=f"(hi) : "l"(v));
    return make_float2(lo, hi);
}
__device__ __forceinline__ void mma_bf16(float* c, const uint32_t* a,
                                         uint32_t b0, uint32_t b1) {
    asm volatile(
        "mma.sync.aligned.m16n8k16.row.col.f32.bf16.bf16.f32 "
        "{%0,%1,%2,%3},{%4,%5,%6,%7},{%8,%9},{%0,%1,%2,%3};"
        : "+f"(c[0]), "+f"(c[1]), "+f"(c[2]), "+f"(c[3])
        : "r"(a[0]), "r"(a[1]), "r"(a[2]), "r"(a[3]), "r"(b0), "r"(b1));
}
// Validated helper: NON-trans ldmatrix.
__device__ __forceinline__ void ldsm4(uint32_t* r, uint32_t addr) {
    asm volatile("ldmatrix.sync.aligned.m8n8.x4.shared.b16 {%0,%1,%2,%3},[%4];"
                 : "=r"(r[0]), "=r"(r[1]), "=r"(r[2]), "=r"(r[3]) : "r"(addr));
}
__device__ __forceinline__ void cpa16(uint32_t dst, const void* src) {
    asm volatile("cp.async.cg.shared.global [%0], [%1], 16;" :: "r"(dst), "l"(src));
}
__device__ __forceinline__ void cpa8(uint32_t dst, const void* src) {
    asm volatile("cp.async.ca.shared.global [%0], [%1], 8;" :: "r"(dst), "l"(src));
}
#define CP_COMMIT() asm volatile("cp.async.commit_group;" ::: "memory")
#define CP_WAIT0()  asm volatile("cp.async.wait_group 0;" ::: "memory")

// ---------------- projection kernel (byte-identical to R16) -----------------
__global__ void __launch_bounds__(256, 3) proj_kernel(
    const float* __restrict__ x,
    const float* __restrict__ wq, const float* __restrict__ bq,
    const float* __restrict__ wk, const float* __restrict__ bk,
    const float* __restrict__ wv, const float* __restrict__ bv)
{
    __shared__ float xs[32][256];
    __shared__ unsigned long long ws2[32][34];   // [c][o] duplicated (w,w) pairs

    const int b  = blockIdx.z;
    const int n0 = blockIdx.x * 256;
    const int o0 = blockIdx.y * 32;
    const int tid = threadIdx.x;
    const int tx = tid & 63;
    const int ty = tid >> 6;

    unsigned long long accp[8][2];
#pragma unroll
    for (int i = 0; i < 8; i++) { accp[i][0] = 0ull; accp[i][1] = 0ull; }

    for (int cc = 0; cc < NC; cc += 32) {
        __syncthreads();
#pragma unroll
        for (int p = 0; p < 8; p++) {
            int idx = tid + p * 256;
            int c  = idx >> 6;
            int n4 = idx & 63;
            *(float4*)&xs[c][n4 * 4] =
                *(const float4*)&x[(size_t)(b * NC + cc + c) * NN + n0 + n4 * 4];
        }
#pragma unroll
        for (int p = 0; p < 4; p++) {
            int idx = tid + p * 256;
            int o  = idx >> 5;
            int c2 = idx & 31;
            int og = o0 + o;
            const float* wsrc;
            if (og < 32)        wsrc = wq + og * NC;
            else if (og < 64)   wsrc = wk + (og - 32) * NC;
            else                wsrc = wv + (og - 64) * NC;
            float v = wsrc[cc + c2];
            ws2[c2][o] = pack2(v, v);
        }
        __syncthreads();
#pragma unroll
        for (int c = 0; c < 32; c++) {
            ulonglong2 xp = *(const ulonglong2*)&xs[c][tx * 4];
            ulonglong2 wa = *(const ulonglong2*)&ws2[c][ty * 8];
            ulonglong2 wb = *(const ulonglong2*)&ws2[c][ty * 8 + 2];
            ulonglong2 wc = *(const ulonglong2*)&ws2[c][ty * 8 + 4];
            ulonglong2 wd = *(const ulonglong2*)&ws2[c][ty * 8 + 6];
            fma2(accp[0][0], wa.x, xp.x); fma2(accp[0][1], wa.x, xp.y);
            fma2(accp[1][0], wa.y, xp.x); fma2(accp[1][1], wa.y, xp.y);
            fma2(accp[2][0], wb.x, xp.x); fma2(accp[2][1], wb.x, xp.y);
            fma2(accp[3][0], wb.y, xp.x); fma2(accp[3][1], wb.y, xp.y);
            fma2(accp[4][0], wc.x, xp.x); fma2(accp[4][1], wc.x, xp.y);
            fma2(accp[5][0], wc.y, xp.x); fma2(accp[5][1], wc.y, xp.y);
            fma2(accp[6][0], wd.x, xp.x); fma2(accp[6][1], wd.x, xp.y);
            fma2(accp[7][0], wd.y, xp.x); fma2(accp[7][1], wd.y, xp.y);
        }
    }

    float acc[8][4];
#pragma unroll
    for (int i = 0; i < 8; i++) {
        float2 f0 = unpack2(accp[i][0]);
        float2 f1 = unpack2(accp[i][1]);
        acc[i][0] = f0.x; acc[i][1] = f0.y; acc[i][2] = f1.x; acc[i][3] = f1.y;
    }

    if (o0 < 64) {
        const float* bias = (o0 == 0) ? bq : bk;
        __syncthreads();
#pragma unroll
        for (int i = 0; i < 8; i++) {
            int o = ty * 8 + i;
            float bs = bias[o];
#pragma unroll
            for (int j = 0; j < 4; j++)
                xs[o][tx * 4 + j] = acc[i][j] + bs;
        }
        __syncthreads();
        const int n = tid;
        uint32_t hi[16], lo[16];
#pragma unroll
        for (int d2 = 0; d2 < 16; d2++) {
            float v0 = xs[2 * d2][n], v1 = xs[2 * d2 + 1][n];
            float h0 = bfh(v0), h1 = bfh(v1);
            hi[d2] = bf2pack(h0, h1);
            lo[d2] = bf2pack(v0 - h0, v1 - h1);
        }
        __nv_bfloat16* dh = ((o0 == 0) ? qth : kth) + ((size_t)b * NN + n0 + n) * 32;
        __nv_bfloat16* dl = ((o0 == 0) ? qtl : ktl) + ((size_t)b * NN + n0 + n) * 32;
#pragma unroll
        for (int q4 = 0; q4 < 4; q4++) {
            *(uint4*)&dh[q4 * 8] = ((const uint4*)hi)[q4];
            *(uint4*)&dl[q4 * 8] = ((const uint4*)lo)[q4];
        }
    } else {
#pragma unroll
        for (int i = 0; i < 8; i++) {
            int ch = o0 - 64 + ty * 8 + i;
            float bs = bv[ch];
            float vals[4] = {acc[i][0]+bs, acc[i][1]+bs, acc[i][2]+bs, acc[i][3]+bs};
            uint32_t hp[2], lp[2];
#pragma unroll
            for (int p = 0; p < 2; p++) {
                float h0 = bfh(vals[2*p]), h1 = bfh(vals[2*p+1]);
                hp[p] = bf2pack(h0, h1);
                lp[p] = bf2pack(vals[2*p] - h0, vals[2*p+1] - h1);
            }
            size_t off = ((size_t)b * NC + ch) * NN + n0 + tx * 4;
            *(uint32_t*)&vv_h[off]     = hp[0];
            *(uint32_t*)&vv_h[off + 2] = hp[1];
            *(uint32_t*)&vv_l[off]     = lp[0];
            *(uint32_t*)&vv_l[off + 2] = lp[1];
        }
    }
}

// ---------------- fused attention kernel (cg-dedup QK via P exchange) -------
// smem bytes:
//   [0,     20480)  Q stage  bf16 [2 limb][128 rows][40] (80B row stride)
//   [20480, 40960)  K tiles  bf16 [4 buf][2 limb][32 keys][40]
//   [40960, 172032) V tiles  bf16 [4 buf][2 limb][256 ch][32] (period-8 swizzle)
//   [172032,204800) P exchange [2 parity][16 warps][{PH 512B, PL 512B}]
//   epilogue staging [256][68] f32 reuses [0, 69632)
#define QS_OFF 0
#define QL_REL 10240
#define KS_OFF 20480
#define VS_OFF 40960
#define PEX_OFF 172032
#define SMEM_BYTES 204800

__global__ void __launch_bounds__(NT, 1) attn_kernel(float* __restrict__ out,
                                                     const float* __restrict__ gamma)
{
    extern __shared__ char smem[];
    const uint32_t sb = smem_u32(smem);

    const int b    = blockIdx.y;
    const int n0   = blockIdx.x * MR;
    const int tid  = threadIdx.x;
    const int w    = tid >> 5;
    const int lane = tid & 31;
    const int mg   = w >> 1;          // row group 0..7 (16 rows each)
    const int cg   = w & 1;           // channel group 0..1 (128 ch each)
    const int lq   = lane >> 2;       // lane/4
    const int lr   = lane & 3;        // lane%4
    const int g    = lane >> 3;       // ldmatrix group
    const int gr   = lane & 7;

    // ---- stage Q (both limbs): 128 rows x 4 segs, one per thread ----
    {
        int row = tid >> 2, seg = tid & 3;
        size_t go = ((size_t)b * NN + n0 + row) * 32 + seg * 8;
        *(uint4*)(smem + QS_OFF +          row * 80 + seg * 16) = *(const uint4*)&qth[go];
        *(uint4*)(smem + QS_OFF + QL_REL + row * 80 + seg * 16) = *(const uint4*)&qtl[go];
    }

    // ---- async tile loads; V swizzle period-8: kqs = kq ^ ((ch>>1)&3) ----
#define LOAD_TILE(BUF, M1) do { \
    { \
        int limb = tid >> 8; \
        int rem  = tid & 255; \
        int key  = rem >> 3, dseg = rem & 7; \
        const __nv_bfloat16* ksrc = limb ? ktl : kth; \
        cpa8(sb + KS_OFF + (BUF) * 5120 + limb * 2560 + key * 80 + dseg * 8, \
             &ksrc[((size_t)b * NN + (M1) + key) * 32 + dseg * 4]); \
    } \
    _Pragma("unroll") \
    for (int i = 0; i < 4; i++) { \
        int idx = tid + i * NT; \
        int vl  = idx >> 10; \
        int r2  = idx & 1023; \
        int ch  = r2 >> 2, kq = r2 & 3; \
        int kqs = kq ^ ((ch >> 1) & 3); \
        const __nv_bfloat16* vsrc = vl ? vv_l : vv_h; \
        cpa16(sb + VS_OFF + ((BUF) * 2 + vl) * 16384 + ch * 64 + kqs * 16, \
              &vsrc[((size_t)b * NC + ch) * NN + (M1) + kq * 8]); \
    } \
    CP_COMMIT(); \
} while (0)

    LOAD_TILE(0, 0);
    LOAD_TILE(1, TK);
    CP_WAIT0();
    __syncthreads();

    // ---- hoist Q A-fragments via direct LDS.32 ----
    uint32_t QH[2][4], QL[2][4];
    {
        const char* q0 = smem + QS_OFF + (mg * 16 + lq) * 80;
        const char* q8 = q0 + 8 * 80;
#pragma unroll
        for (int ks = 0; ks < 2; ks++) {
            int d0 = (ks * 16 + 2 * lr) * 2;   // byte offset, 4B aligned
            QH[ks][0] = *(const uint32_t*)(q0 + d0);
            QH[ks][1] = *(const uint32_t*)(q8 + d0);
            QH[ks][2] = *(const uint32_t*)(q0 + d0 + 16);
            QH[ks][3] = *(const uint32_t*)(q8 + d0 + 16);
            QL[ks][0] = *(const uint32_t*)(q0 + QL_REL + d0);
            QL[ks][1] = *(const uint32_t*)(q8 + QL_REL + d0);
            QL[ks][2] = *(const uint32_t*)(q0 + QL_REL + d0 + 16);
            QL[ks][3] = *(const uint32_t*)(q8 + QL_REL + d0 + 16);
        }
    }

    float O[16][4];
#pragma unroll
    for (int i = 0; i < 16; i++)
#pragma unroll
        for (int j = 0; j < 4; j++) O[i][j] = 0.f;
    float lsum0 = 0.f, lsum1 = 0.f;

    const int chL = cg * 128 + ((g >> 1) << 3) + gr;

    // ---- per-tile compute: own-kg QK+exp+pack, P exchange, both PVs ----
    auto compute_tile = [&](int buf, int par) {
        // ---- QK for OWN key-group (kg = cg) ----
        float e0[4] = {0,0,0,0}, e1[4] = {0,0,0,0};
        {
            const char* kbh = smem + KS_OFF + buf * 5120;    // hi limb
            const char* kbl = kbh + 2560;                    // lo limb
            const int r0 = (cg * 16 + lq) * 80;              // keys n=lq (0-7)
            const int r8 = r0 + 640;                         // keys 8-15
            const int db = 4 * lr;
            uint32_t kh[8], kl[8];
            kh[0] = *(const uint32_t*)(kbh + r0 + db);
            kh[1] = *(const uint32_t*)(kbh + r0 + db + 16);
            kh[2] = *(const uint32_t*)(kbh + r0 + db + 32);
            kh[3] = *(const uint32_t*)(kbh + r0 + db + 48);
            kh[4] = *(const uint32_t*)(kbh + r8 + db);
            kh[5] = *(const uint32_t*)(kbh + r8 + db + 16);
            kh[6] = *(const uint32_t*)(kbh + r8 + db + 32);
            kh[7] = *(const uint32_t*)(kbh + r8 + db + 48);
            kl[0] = *(const uint32_t*)(kbl + r0 + db);
            kl[1] = *(const uint32_t*)(kbl + r0 + db + 16);
            kl[2] = *(const uint32_t*)(kbl + r0 + db + 32);
            kl[3] = *(const uint32_t*)(kbl + r0 + db + 48);
            kl[4] = *(const uint32_t*)(kbl + r8 + db);
            kl[5] = *(const uint32_t*)(kbl + r8 + db + 16);
            kl[6] = *(const uint32_t*)(kbl + r8 + db + 32);
            kl[7] = *(const uint32_t*)(kbl + r8 + db + 48);
            // hh
            mma_bf16(e0, QH[0], kh[0], kh[1]);
            mma_bf16(e0, QH[1], kh[2], kh[3]);
            mma_bf16(e1, QH[0], kh[4], kh[5]);
            mma_bf16(e1, QH[1], kh[6], kh[7]);
            // lh (Q lo x K hi)
            mma_bf16(e0, QL[0], kh[0], kh[1]);
            mma_bf16(e0, QL[1], kh[2], kh[3]);
            mma_bf16(e1, QL[0], kh[4], kh[5]);
            mma_bf16(e1, QL[1], kh[6], kh[7]);
            // hl (Q hi x K lo)
            mma_bf16(e0, QH[0], kl[0], kl[1]);
            mma_bf16(e0, QH[1], kl[2], kl[3]);
            mma_bf16(e1, QH[0], kl[4], kl[5]);
            mma_bf16(e1, QH[1], kl[6], kl[7]);
        }

        // ---- softmax numerators + bf16 split P (own kg only) ----
        float p00 = __expf(e0[0]), p01 = __expf(e0[1]);
        float p02 = __expf(e0[2]), p03 = __expf(e0[3]);
        float p10 = __expf(e1[0]), p11 = __expf(e1[1]);
        float p12 = __expf(e1[2]), p13 = __expf(e1[3]);
        lsum0 += p00 + p01 + p10 + p11;
        lsum1 += p02 + p03 + p12 + p13;

        uint32_t PHo[4], PLo[4];
        {
            float h0, h1;
            h0 = bfh(p00); h1 = bfh(p01);
            PHo[0] = bf2pack(h0, h1); PLo[0] = bf2pack(p00 - h0, p01 - h1);
            h0 = bfh(p02); h1 = bfh(p03);
            PHo[1] = bf2pack(h0, h1); PLo[1] = bf2pack(p02 - h0, p03 - h1);
            h0 = bfh(p10); h1 = bfh(p11);
            PHo[2] = bf2pack(h0, h1); PLo[2] = bf2pack(p10 - h0, p11 - h1);
            h0 = bfh(p12); h1 = bfh(p13);
            PHo[3] = bf2pack(h0, h1); PLo[3] = bf2pack(p12 - h0, p13 - h1);
        }

        // ---- exchange P with cg-partner warp (w^1) ----
        {
            char* slot = smem + PEX_OFF + par * 16384 + w * 1024 + lane * 16;
            *(uint4*)(slot)       = make_uint4(PHo[0], PHo[1], PHo[2], PHo[3]);
            *(uint4*)(slot + 512) = make_uint4(PLo[0], PLo[1], PLo[2], PLo[3]);
        }
        asm volatile("bar.sync %0, 64;" :: "r"(mg + 1) : "memory");
        uint32_t PHp[4], PLp[4];
        {
            const char* pslot = smem + PEX_OFF + par * 16384 + (w ^ 1) * 1024 + lane * 16;
            uint4 h4 = *(const uint4*)(pslot);
            uint4 l4 = *(const uint4*)(pslot + 512);
            PHp[0] = h4.x; PHp[1] = h4.y; PHp[2] = h4.z; PHp[3] = h4.w;
            PLp[0] = l4.x; PLp[1] = l4.y; PLp[2] = l4.z; PLp[3] = l4.w;
        }

        // ---- PV pass A: own kg; pass B: partner kg ----
#pragma unroll
        for (int pass = 0; pass < 2; pass++) {
            const int kg = cg ^ pass;
            const uint32_t* PH = pass ? PHp : PHo;
            const uint32_t* PL = pass ? PLp : PLo;
            const int kblk = kg * 2 + (g & 1);
#pragma unroll
            for (int np = 0; np < 8; np++) {
                int ch = chL + np * 16;
                uint32_t row_off = (uint32_t)(ch * 64 + ((kblk ^ ((ch >> 1) & 3)) * 16));
                uint32_t ah = sb + VS_OFF + (buf * 2 + 0) * 16384 + row_off;
                uint32_t al = sb + VS_OFF + (buf * 2 + 1) * 16384 + row_off;
                uint32_t vh[4], vl[4];
                ldsm4(vh, ah);
                ldsm4(vl, al);
#pragma unroll
                for (int u = 0; u < 2; u++) {
                    float* o = O[np * 2 + u];
                    mma_bf16(o, PH, vh[2*u], vh[2*u + 1]);
                    mma_bf16(o, PH, vl[2*u], vl[2*u + 1]);
                    mma_bf16(o, PL, vh[2*u], vh[2*u + 1]);
                }
            }
        }
    };

    // ---- main loop: pairs of tiles, one wait+barrier per pair ----
    for (int t = 0; t < NN / TK; t += 2) {
        if (t + 2 < NN / TK) LOAD_TILE((t + 2) & 3, (t + 2) * TK);
        if (t + 3 < NN / TK) LOAD_TILE((t + 3) & 3, (t + 3) * TK);
        compute_tile(t & 3, 0);
        compute_tile((t + 1) & 3, 1);
        CP_WAIT0();
        __syncthreads();
    }

    // ---- lsum: combine with cg-partner (covers the other key-group) ----
    {
        float* lex = (float*)(smem + PEX_OFF);
        lex[(w * 32 + lane) * 2]     = lsum0;
        lex[(w * 32 + lane) * 2 + 1] = lsum1;
        __syncthreads();
        lsum0 += lex[((w ^ 1) * 32 + lane) * 2];
        lsum1 += lex[((w ^ 1) * 32 + lane) * 2 + 1];
    }

    // ---- row-sum reduce over lane quads ----
    lsum0 += __shfl_xor_sync(0xffffffffu, lsum0, 1);
    lsum0 += __shfl_xor_sync(0xffffffffu, lsum0, 2);
    lsum1 += __shfl_xor_sync(0xffffffffu, lsum1, 1);
    lsum1 += __shfl_xor_sync(0xffffffffu, lsum1, 2);
    const float inv0 = 1.0f / lsum0;
    const float inv1 = 1.0f / lsum1;
    const float gm = __ldg(gamma);

    // ---- epilogue: two 64-row passes through [256][68] f32 staging ----
    float* stg = (float*)smem;
#pragma unroll
    for (int half = 0; half < 2; half++) {
        __syncthreads();
        if ((mg >> 2) == half) {
#pragma unroll
            for (int oc = 0; oc < 16; oc++) {
                int ch = cg * 128 + oc * 8 + lr * 2;
                int r0 = mg * 16 + lq - half * 64, r1 = r0 + 8;
                float o0 = O[oc][0] * inv0, o1 = O[oc][1] * inv0;
                float o2 = O[oc][2] * inv1, o3 = O[oc][3] * inv1;
                stg[ ch      * 68 + r0] = floorf((gm * o0 + o0) * 256.f) * 0.00390625f;
                stg[(ch + 1) * 68 + r0] = floorf((gm * o1 + o1) * 256.f) * 0.00390625f;
                stg[ ch      * 68 + r1] = floorf((gm * o2 + o2) * 256.f) * 0.00390625f;
                stg[(ch + 1) * 68 + r1] = floorf((gm * o3 + o3) * 256.f) * 0.00390625f;
            }
        }
        __syncthreads();
#pragma unroll
        for (int i = 0; i < 8; i++) {
            int ch = (tid >> 4) + i * 32;
            int r4 = (tid & 15) * 4;
            *(float4*)&out[((size_t)b * NC + ch) * NN + n0 + half * 64 + r4] =
                *(float4*)&stg[ch * 68 + r4];
        }
    }
}

// ---------------- launch ----------------
extern "C" void kernel_launch(void* const* d_in, const int* in_sizes, int n_in,
                              void* d_out, int out_size)
{
    const float* x     = (const float*)d_in[0];
    const float* wq    = (const float*)d_in[1];
    const float* bq    = (const float*)d_in[2];
    const float* wk    = (const float*)d_in[3];
    const float* bk    = (const float*)d_in[4];
    const float* wv    = (const float*)d_in[5];
    const float* bv    = (const float*)d_in[6];
    const float* gamma = (const float*)d_in[7];
    float* out = (float*)d_out;

    dim3 gp(NN / 256, 10, NB);
    proj_kernel<<<gp, 256>>>(x, wq, bq, wk, bk, wv, bv);

    cudaFuncSetAttribute(attn_kernel, cudaFuncAttributeMaxDynamicSharedMemorySize, SMEM_BYTES);
    dim3 ga(NN / MR, NB);
    attn_kernel<<<ga, NT, SMEM_BYTES>>>(out, gamma);
}